// round 1
// baseline (speedup 1.0000x reference)
#include <cuda_runtime.h>
#include <cuda_bf16.h>
#include <math.h>

// ---------------------------------------------------------------------------
// MutationMLMLossModel
//   inputs (metadata order):
//     0: mlm_outputs     float32 [B, S, V]   (B=256, S=4096, V=30)
//     1: nsp_outputs     float32 [B, 2]
//     2: mutation_matrix float32 [V, V]      (mathematically unused)
//     3: mlm_targets     int32   [B, S]
//     4: is_nexts        int32   [B]         (unused)
//   output (flattened tuple, float32):
//     [0, B*S)        mlm_predictions (argmax over V, first-max tiebreak)
//     [B*S, B*S+B)    nsp_predictions (argmax over 2)
//     [B*S+B]         loss = sum_{t!=0} nll / (B*S)
// ---------------------------------------------------------------------------

__device__ double g_loss_accum;

// Kernel A: zero accumulator + nsp argmax
__global__ void prologue_kernel(const float* __restrict__ nsp,
                                float* __restrict__ out_nsp,
                                int B) {
    int b = blockIdx.x * blockDim.x + threadIdx.x;
    if (b == 0) g_loss_accum = 0.0;
    if (b < B) {
        float v0 = nsp[2 * b + 0];
        float v1 = nsp[2 * b + 1];
        // argmax with first-max tiebreak: index 1 only if strictly greater
        out_nsp[b] = (v1 > v0) ? 1.0f : 0.0f;
    }
}

// Kernel B: one warp per row (grid-stride). lanes 0..29 hold the 30 logits.
__global__ void __launch_bounds__(256) mlm_row_kernel(
    const float* __restrict__ logits,   // [N, 30]
    const int* __restrict__ targets,    // [N]
    float* __restrict__ out_pred,       // [N]
    long long N) {
    const unsigned FULL = 0xFFFFFFFFu;
    const int V = 30;

    int lane = threadIdx.x & 31;
    int warp_in_block = threadIdx.x >> 5;
    long long gwarp = (long long)blockIdx.x * (blockDim.x >> 5) + warp_in_block;
    long long nwarps = (long long)gridDim.x * (blockDim.x >> 5);

    float local_sum = 0.0f;  // meaningful on lane 0

    for (long long r = gwarp; r < N; r += nwarps) {
        const float* row = logits + r * V;
        float val = (lane < V) ? __ldg(row + lane) : -INFINITY;

        // --- warp argmax with first-max (lowest-index) tiebreak ---
        float mv = val;
        int mi = (lane < V) ? lane : 31;
        #pragma unroll
        for (int off = 16; off > 0; off >>= 1) {
            float ov = __shfl_down_sync(FULL, mv, off);
            int   oi = __shfl_down_sync(FULL, mi, off);
            if (ov > mv || (ov == mv && oi < mi)) { mv = ov; mi = oi; }
        }
        float rmax = __shfl_sync(FULL, mv, 0);
        int   amax = __shfl_sync(FULL, mi, 0);

        // --- warp sum of exp(x - max) ---
        float e = (lane < V) ? __expf(val - rmax) : 0.0f;
        #pragma unroll
        for (int off = 16; off > 0; off >>= 1)
            e += __shfl_xor_sync(FULL, e, off);
        // e now holds the full sum on every lane

        // --- target gather ---
        int t = 0;
        if (lane == 0) t = __ldg(targets + r);
        t = __shfl_sync(FULL, t, 0);
        float xt = __shfl_sync(FULL, val, t);   // x[target]

        if (lane == 0) {
            out_pred[r] = (float)amax;
            if (t != 0) {
                float lse = rmax + logf(e);
                local_sum += (lse - xt);        // nll
            }
        }
    }

    // --- block reduction of lane-0 partials, one atomic per block ---
    __shared__ float s_partial[8];
    if (lane == 0) s_partial[warp_in_block] = local_sum;
    __syncthreads();
    if (threadIdx.x == 0) {
        float bs = 0.0f;
        int nw = blockDim.x >> 5;
        for (int i = 0; i < nw; i++) bs += s_partial[i];
        atomicAdd(&g_loss_accum, (double)bs);
    }
}

// Kernel C: finalize loss
__global__ void epilogue_kernel(float* __restrict__ out_loss, long long N) {
    if (threadIdx.x == 0 && blockIdx.x == 0) {
        out_loss[0] = (float)(g_loss_accum / (double)N);
    }
}

extern "C" void kernel_launch(void* const* d_in, const int* in_sizes, int n_in,
                              void* d_out, int out_size) {
    const float* mlm      = (const float*)d_in[0];   // B*S*V
    const float* nsp      = (const float*)d_in[1];   // B*2
    const int*   targets  = (const int*)d_in[3];     // B*S
    float* out = (float*)d_out;

    long long N = (long long)in_sizes[3];            // B*S rows
    int B = in_sizes[4];                              // batch

    float* out_pred = out;                 // [0, N)
    float* out_nsp  = out + N;             // [N, N+B)
    float* out_loss = out + N + B;         // [N+B]

    // A: zero accumulator + nsp predictions
    int ta = 256;
    int ga = (B + ta - 1) / ta;
    prologue_kernel<<<ga, ta>>>(nsp, out_nsp, B);

    // B: main row kernel. 2048 blocks x 256 threads = 16384 warps,
    // ~64 rows per warp -> only 2048 loss atomics.
    mlm_row_kernel<<<2048, 256>>>(mlm, targets, out_pred, N);

    // C: finalize
    epilogue_kernel<<<1, 32>>>(out_loss, N);
}

// round 2
// speedup vs baseline: 2.9049x; 2.9049x over previous
#include <cuda_runtime.h>
#include <cuda_bf16.h>
#include <math.h>

// ---------------------------------------------------------------------------
// MutationMLMLossModel
//   inputs (metadata order):
//     0: mlm_outputs     float32 [B, S, V]   (B=256, S=4096, V=30)
//     1: nsp_outputs     float32 [B, 2]
//     2: mutation_matrix float32 [V, V]      (mathematically unused)
//     3: mlm_targets     int32   [B, S]
//     4: is_nexts        int32   [B]         (unused)
//   output (flattened tuple, float32):
//     [0, N)        mlm_predictions (argmax over V, first-max tiebreak)
//     [N, N+B)      nsp_predictions (argmax over 2)
//     [N+B]         loss = sum_{t!=0} (lse - x[t]) / N
// ---------------------------------------------------------------------------

#define V        30
#define TILE     256          // rows per block
#define THREADS  256
#define SSTRIDE  31           // odd stride -> conflict-free column access

#define MAX_BLOCKS 32768
__device__ double g_partials[MAX_BLOCKS];

// Main kernel: stage a 256-row tile in smem (coalesced float4 loads),
// then thread t computes row t serially.
__global__ void __launch_bounds__(THREADS) mlm_tile_kernel(
    const float* __restrict__ logits,   // [N, V]
    const int*   __restrict__ targets,  // [N]
    float*       __restrict__ out_pred, // [N]
    long long N)
{
    __shared__ float s[TILE * SSTRIDE];     // 31744 B
    __shared__ float s_red[THREADS / 32];

    const int tid = threadIdx.x;
    const long long tile_base = (long long)blockIdx.x * TILE;
    const int rows = (int)((N - tile_base) < TILE ? (N - tile_base) : TILE);
    const float* gbase = logits + tile_base * (long long)V;

    // ---- stage tile: global (row-major, 30 floats/row) -> smem stride-31 ----
    // flat element f of the tile maps to smem index f + f/30.
    if (rows == TILE) {
        const float4* g4 = (const float4*)gbase;   // tile base is 16B-aligned
        for (int idx = tid; idx < (TILE * V) / 4; idx += THREADS) {
            float4 v = g4[idx];
            int f = idx * 4;
            s[(f + 0) + (f + 0) / V] = v.x;
            s[(f + 1) + (f + 1) / V] = v.y;
            s[(f + 2) + (f + 2) / V] = v.z;
            s[(f + 3) + (f + 3) / V] = v.w;
        }
    } else {
        for (int f = tid; f < rows * V; f += THREADS)
            s[f + f / V] = gbase[f];
    }
    __syncthreads();

    // ---- per-thread row compute ----
    float nll = 0.0f;
    if (tid < rows) {
        const float* row = s + tid * SSTRIDE;

        float best = row[0];
        int   bi   = 0;
        #pragma unroll
        for (int j = 1; j < V; j++) {
            float x = row[j];
            if (x > best) { best = x; bi = j; }   // strict > keeps first max
        }

        float sum = 0.0f;
        #pragma unroll
        for (int j = 0; j < V; j++)
            sum += __expf(row[j] - best);

        int t = __ldg(targets + tile_base + tid);
        out_pred[tile_base + tid] = (float)bi;
        if (t != 0)
            nll = best + __logf(sum) - row[t];
    }

    // ---- block reduction -> one double partial per block ----
    const unsigned FULL = 0xFFFFFFFFu;
    float w = nll;
    #pragma unroll
    for (int off = 16; off > 0; off >>= 1)
        w += __shfl_xor_sync(FULL, w, off);
    if ((tid & 31) == 0) s_red[tid >> 5] = w;
    __syncthreads();
    if (tid == 0) {
        float bs = 0.0f;
        #pragma unroll
        for (int i = 0; i < THREADS / 32; i++) bs += s_red[i];
        g_partials[blockIdx.x] = (double)bs;
    }
}

// Epilogue: sum block partials + nsp argmax. One block.
__global__ void __launch_bounds__(256) epilogue_kernel(
    const float* __restrict__ nsp,
    float* __restrict__ out_nsp,
    float* __restrict__ out_loss,
    int B, int nblocks, long long N)
{
    __shared__ double s_red[8];
    const int tid = threadIdx.x;

    for (int b = tid; b < B; b += blockDim.x) {
        float v0 = nsp[2 * b + 0];
        float v1 = nsp[2 * b + 1];
        out_nsp[b] = (v1 > v0) ? 1.0f : 0.0f;
    }

    double acc = 0.0;
    for (int i = tid; i < nblocks; i += blockDim.x)
        acc += g_partials[i];

    const unsigned FULL = 0xFFFFFFFFu;
    #pragma unroll
    for (int off = 16; off > 0; off >>= 1)
        acc += __shfl_xor_sync(FULL, acc, off);
    if ((tid & 31) == 0) s_red[tid >> 5] = acc;
    __syncthreads();
    if (tid == 0) {
        double total = 0.0;
        #pragma unroll
        for (int i = 0; i < 8; i++) total += s_red[i];
        out_loss[0] = (float)(total / (double)N);
    }
}

extern "C" void kernel_launch(void* const* d_in, const int* in_sizes, int n_in,
                              void* d_out, int out_size) {
    const float* mlm     = (const float*)d_in[0];
    const float* nsp     = (const float*)d_in[1];
    const int*   targets = (const int*)d_in[3];
    float* out = (float*)d_out;

    long long N = (long long)in_sizes[3];   // B*S rows
    int B = in_sizes[4];

    float* out_pred = out;          // [0, N)
    float* out_nsp  = out + N;      // [N, N+B)
    float* out_loss = out + N + B;  // [N+B]

    int nblocks = (int)((N + TILE - 1) / TILE);   // 4096 for the given shape
    if (nblocks > MAX_BLOCKS) nblocks = MAX_BLOCKS;  // (not reachable for this problem)

    mlm_tile_kernel<<<nblocks, THREADS>>>(mlm, targets, out_pred, N);
    epilogue_kernel<<<1, 256>>>(nsp, out_nsp, out_loss, B, nblocks, N);
}

// round 4
// speedup vs baseline: 4.7572x; 1.6377x over previous
#include <cuda_runtime.h>
#include <cuda_bf16.h>
#include <math.h>

// ---------------------------------------------------------------------------
// MutationMLMLossModel — fused single-kernel version
//   inputs (metadata order):
//     0: mlm_outputs     float32 [B, S, V]   (B=256, S=4096, V=30)
//     1: nsp_outputs     float32 [B, 2]
//     2: mutation_matrix float32 [V, V]      (mathematically unused)
//     3: mlm_targets     int32   [B, S]
//     4: is_nexts        int32   [B]         (unused)
//   output (float32): [0,N) mlm argmax | [N,N+B) nsp argmax | [N+B] loss
// ---------------------------------------------------------------------------

#define V        30
#define TILE     256
#define THREADS  256
#define NBLOCKS  2048

__device__ double   g_partials[NBLOCKS];
__device__ unsigned g_ticket;          // zero-init; last block resets to 0

__global__ void __launch_bounds__(THREADS) fused_kernel(
    const float* __restrict__ logits,   // [N, V]
    const int*   __restrict__ targets,  // [N]
    const float* __restrict__ nsp,      // [B, 2]
    float*       __restrict__ out_pred, // [N]
    float*       __restrict__ out_nsp,  // [B]
    float*       __restrict__ out_loss, // [1]
    long long N, int B)
{
    __shared__ float  s[TILE * V];          // 30720 B, raw row-major
    __shared__ float  s_red[THREADS / 32];
    __shared__ double s_dred[THREADS / 32];
    __shared__ int    s_islast;

    const int tid = threadIdx.x;
    float thread_nll = 0.0f;

    for (long long tile_base = (long long)blockIdx.x * TILE; tile_base < N;
         tile_base += (long long)gridDim.x * TILE) {

        const int rows = (int)(((N - tile_base) < TILE) ? (N - tile_base) : TILE);

        // ---- stage tile: coalesced float4 global -> raw smem (STS.128) ----
        if (rows == TILE) {
            const float4* g4 = (const float4*)(logits + tile_base * (long long)V);
            float4* s4 = (float4*)s;
            #pragma unroll 8
            for (int idx = tid; idx < (TILE * V) / 4; idx += THREADS)
                s4[idx] = g4[idx];
        } else {
            const float* g = logits + tile_base * (long long)V;
            for (int f = tid; f < rows * V; f += THREADS)
                s[f] = g[f];
        }
        __syncthreads();

        // ---- thread t = row t: 15 conflict-free LDS.64 into registers ----
        if (tid < rows) {
            const int t = __ldg(targets + tile_base + tid);

            float x[V];
            const float2* row2 = (const float2*)(s + tid * V);
            #pragma unroll
            for (int j = 0; j < V / 2; j++) {
                float2 v = row2[j];
                x[2 * j]     = v.x;
                x[2 * j + 1] = v.y;
            }

            float best = x[0];
            int   bi   = 0;
            float tv   = x[0];
            #pragma unroll
            for (int j = 1; j < V; j++) {
                if (x[j] > best) { best = x[j]; bi = j; }  // strict >: first max
                if (j == t) tv = x[j];
            }

            float sum = 0.0f;
            #pragma unroll
            for (int j = 0; j < V; j++)
                sum += __expf(x[j] - best);

            out_pred[tile_base + tid] = (float)bi;
            if (t != 0)
                thread_nll += best + __logf(sum) - tv;
        }
        __syncthreads();   // protect smem before next tile
    }

    // ---- block reduction -> one double partial per block ----
    const unsigned FULL = 0xFFFFFFFFu;
    float w = thread_nll;
    #pragma unroll
    for (int off = 16; off > 0; off >>= 1)
        w += __shfl_xor_sync(FULL, w, off);
    if ((tid & 31) == 0) s_red[tid >> 5] = w;
    __syncthreads();
    if (tid == 0) {
        float bs = 0.0f;
        #pragma unroll
        for (int i = 0; i < THREADS / 32; i++) bs += s_red[i];
        g_partials[blockIdx.x] = (double)bs;
        __threadfence();
        unsigned ticket = atomicAdd(&g_ticket, 1u);
        s_islast = (ticket == gridDim.x - 1);
    }
    __syncthreads();

    // ---- last block: nsp argmax + final loss + ticket reset ----
    if (s_islast) {
        for (int b = tid; b < B; b += THREADS) {
            float v0 = nsp[2 * b + 0];
            float v1 = nsp[2 * b + 1];
            out_nsp[b] = (v1 > v0) ? 1.0f : 0.0f;
        }

        double acc = 0.0;
        for (int i = tid; i < (int)gridDim.x; i += THREADS)
            acc += g_partials[i];
        #pragma unroll
        for (int off = 16; off > 0; off >>= 1)
            acc += __shfl_xor_sync(FULL, acc, off);
        if ((tid & 31) == 0) s_dred[tid >> 5] = acc;
        __syncthreads();
        if (tid == 0) {
            double total = 0.0;
            #pragma unroll
            for (int i = 0; i < THREADS / 32; i++) total += s_dred[i];
            out_loss[0] = (float)(total / (double)N);
            g_ticket = 0;                    // reset for next graph replay
        }
    }
}

extern "C" void kernel_launch(void* const* d_in, const int* in_sizes, int n_in,
                              void* d_out, int out_size) {
    const float* mlm     = (const float*)d_in[0];
    const float* nsp     = (const float*)d_in[1];
    const int*   targets = (const int*)d_in[3];
    float* out = (float*)d_out;

    long long N = (long long)in_sizes[3];   // B*S rows
    int B = in_sizes[4];

    float* out_pred = out;          // [0, N)
    float* out_nsp  = out + N;      // [N, N+B)
    float* out_loss = out + N + B;  // [N+B]

    long long ntiles = (N + TILE - 1) / TILE;
    int nblocks = (ntiles < NBLOCKS) ? (int)ntiles : NBLOCKS;

    fused_kernel<<<nblocks, THREADS>>>(mlm, targets, nsp,
                                       out_pred, out_nsp, out_loss, N, B);
}